// round 2
// baseline (speedup 1.0000x reference)
#include <cuda_runtime.h>
#include <cstdint>
#include <cstddef>

#define BB   8
#define RR   40
#define LL   128
#define INC  256
#define WDIM 512
#define DREL 15
#define FF   200
#define HIDN 300
#define OSP  126

__device__ float g_PQ[BB * 512 * LL];
__device__ float g_mem[(size_t)BB * INC * LL * LL];
__device__ float g_filt2[(size_t)BB * INC * FF * 9];
__device__ float g_h[BB * HIDN];
__device__ float g_trans[BB * FF];
__device__ float g_maxv[BB * FF];

__device__ __forceinline__ float lrelu(float v) { return v >= 0.f ? v : 0.01f * v; }

__device__ __forceinline__ void atomicMaxF(float* addr, float val) {
    int old = __float_as_int(*addr);
    while (__int_as_float(old) < val) {
        int assumed = old;
        old = atomicCAS((int*)addr, assumed, __float_as_int(val));
        if (old == assumed) break;
    }
}

#define PACKF2(out, lo, hi) asm("mov.b64 %0, {%1, %2};" : "=l"(out) : "f"(lo), "f"(hi))
#define UNPACKF2(lo, hi, in) asm("mov.b64 {%0, %1}, %2;" : "=f"(lo), "=f"(hi) : "l"(in))
#define FMA2(d, a, b) asm("fma.rn.f32x2 %0, %1, %2, %0;" : "+l"(d) : "l"(a), "l"(b))

// ============================================================================
// k_small: init g_maxv; h[b][t] = leaky(inputs·ffW[t]+ffb); trans[b][f]
// ============================================================================
__global__ void k_small(const float* __restrict__ e1, const float* __restrict__ e2,
                        const float* __restrict__ ffW, const float* __restrict__ ffb,
                        const float* __restrict__ itW, const float* __restrict__ itb) {
    int gtid = blockIdx.x * blockDim.x + threadIdx.x;
    if (gtid < BB * FF) g_maxv[gtid] = -3.4e38f;
    int w = gtid >> 5;
    int lane = gtid & 31;
    if (w < BB * HIDN) {
        int b = w / HIDN, t = w % HIDN;
        float acc = 0.f;
        for (int k = lane; k < 1024; k += 32) {
            float x = (k < 512) ? e1[b * 512 + k] : e2[b * 512 + k - 512];
            acc = fmaf(x, ffW[t * 1024 + k], acc);
        }
        acc += __shfl_down_sync(0xffffffffu, acc, 16);
        acc += __shfl_down_sync(0xffffffffu, acc, 8);
        acc += __shfl_down_sync(0xffffffffu, acc, 4);
        acc += __shfl_down_sync(0xffffffffu, acc, 2);
        acc += __shfl_down_sync(0xffffffffu, acc, 1);
        if (lane == 0) g_h[b * HIDN + t] = lrelu(acc + ffb[t]);
    } else if (w < BB * HIDN + BB * FF) {
        int idx = w - BB * HIDN;
        int b = idx / FF, f = idx % FF;
        float acc = 0.f;
        for (int k = lane; k < 1024; k += 32) {
            float x = (k < 512) ? e1[b * 512 + k] : e2[b * 512 + k - 512];
            acc = fmaf(x, itW[f * 1024 + k], acc);
        }
        acc += __shfl_down_sync(0xffffffffu, acc, 16);
        acc += __shfl_down_sync(0xffffffffu, acc, 8);
        acc += __shfl_down_sync(0xffffffffu, acc, 4);
        acc += __shfl_down_sync(0xffffffffu, acc, 2);
        acc += __shfl_down_sync(0xffffffffu, acc, 1);
        if (lane == 0) g_trans[b * FF + f] = lrelu(acc + itb[f]);
    }
}

// ============================================================================
// k_pq: PQ[b][o'][j]; o'<256: word_h[b,j,:]·arcW[o',0:512]
//                     o'>=256: word_h[b,j,:]·arcW[o'-256,512:1024]
// ============================================================================
__global__ __launch_bounds__(256) void k_pq(const float* __restrict__ wh,
                                            const float* __restrict__ arcW) {
    int b = blockIdx.z, ot = blockIdx.y, jt = blockIdx.x;
    __shared__ float sW[16][65];
    __shared__ float sH[16][65];
    int tid = threadIdx.x;
    int ty = tid >> 4, tx = tid & 15;
    int lr = tid >> 2;
    int lc4 = (tid & 3) * 4;

    int og = ot * 64 + lr;
    const float* wrow = (og < 256) ? (arcW + (size_t)og * 1039)
                                   : (arcW + (size_t)(og - 256) * 1039 + 512);
    const float* hrow = wh + ((size_t)(b * LL) + jt * 64 + lr) * WDIM;

    float acc[4][4];
#pragma unroll
    for (int r = 0; r < 4; r++)
#pragma unroll
        for (int c = 0; c < 4; c++) acc[r][c] = 0.f;

    for (int k0 = 0; k0 < 512; k0 += 16) {
#pragma unroll
        for (int q = 0; q < 4; q++) sW[lc4 + q][lr] = wrow[k0 + lc4 + q];
        float4 hv = *(const float4*)(hrow + k0 + lc4);
        sH[lc4 + 0][lr] = hv.x;
        sH[lc4 + 1][lr] = hv.y;
        sH[lc4 + 2][lr] = hv.z;
        sH[lc4 + 3][lr] = hv.w;
        __syncthreads();
#pragma unroll
        for (int kk = 0; kk < 16; kk++) {
            float a0 = sW[kk][ty * 4 + 0], a1 = sW[kk][ty * 4 + 1];
            float a2 = sW[kk][ty * 4 + 2], a3 = sW[kk][ty * 4 + 3];
            float b0 = sH[kk][tx * 4 + 0], b1 = sH[kk][tx * 4 + 1];
            float b2 = sH[kk][tx * 4 + 2], b3 = sH[kk][tx * 4 + 3];
            acc[0][0] = fmaf(a0, b0, acc[0][0]); acc[0][1] = fmaf(a0, b1, acc[0][1]);
            acc[0][2] = fmaf(a0, b2, acc[0][2]); acc[0][3] = fmaf(a0, b3, acc[0][3]);
            acc[1][0] = fmaf(a1, b0, acc[1][0]); acc[1][1] = fmaf(a1, b1, acc[1][1]);
            acc[1][2] = fmaf(a1, b2, acc[1][2]); acc[1][3] = fmaf(a1, b3, acc[1][3]);
            acc[2][0] = fmaf(a2, b0, acc[2][0]); acc[2][1] = fmaf(a2, b1, acc[2][1]);
            acc[2][2] = fmaf(a2, b2, acc[2][2]); acc[2][3] = fmaf(a2, b3, acc[2][3]);
            acc[3][0] = fmaf(a3, b0, acc[3][0]); acc[3][1] = fmaf(a3, b1, acc[3][1]);
            acc[3][2] = fmaf(a3, b2, acc[3][2]); acc[3][3] = fmaf(a3, b3, acc[3][3]);
        }
        __syncthreads();
    }
#pragma unroll
    for (int r = 0; r < 4; r++) {
        int og2 = ot * 64 + ty * 4 + r;
#pragma unroll
        for (int c = 0; c < 4; c++) {
            int jg = jt * 64 + tx * 4 + c;
            g_PQ[((size_t)b * 512 + og2) * LL + jg] = acc[r][c];
        }
    }
}

// ============================================================================
// k_arc: mem[b][o][i][j] = leaky( m*(P[b,o,j]+Q[b,o,i]) + T·Wr[o] + bias[o] )
// ============================================================================
__global__ __launch_bounds__(128) void k_arc(const float* __restrict__ energy,
                                             const float* __restrict__ relE,
                                             const float* __restrict__ arcW,
                                             const float* __restrict__ arcB) {
    int i = blockIdx.x, b = blockIdx.y;
    __shared__ float s_rel[RR * DREL];
    __shared__ float s_Wr[INC * DREL];
    __shared__ float s_Q[INC];
    __shared__ float s_b[INC];
    int tid = threadIdx.x;
    for (int idx = tid; idx < RR * DREL; idx += 128) s_rel[idx] = relE[idx];
    for (int idx = tid; idx < INC * DREL; idx += 128) {
        int o = idx / DREL, d = idx % DREL;
        s_Wr[idx] = arcW[(size_t)o * 1039 + 1024 + d];
    }
    for (int idx = tid; idx < INC; idx += 128) {
        s_b[idx] = arcB[idx];
        s_Q[idx] = g_PQ[((size_t)b * 512 + 256 + idx) * LL + i];
    }
    __syncthreads();

    int j = tid;
    float T[DREL];
#pragma unroll
    for (int d = 0; d < DREL; d++) T[d] = 0.f;
    float m = 0.f;
    const float* ep = energy + (((size_t)b * RR) * LL + i) * LL + j;
#pragma unroll 8
    for (int r = 0; r < RR; r++) {
        float e = fmaxf(ep[(size_t)r * (LL * LL)], 0.f);
        m += e;
#pragma unroll
        for (int d = 0; d < DREL; d++) T[d] = fmaf(e, s_rel[r * DREL + d], T[d]);
    }
    const float* pqp = g_PQ + (size_t)b * 512 * LL + j;
    float* outp = g_mem + (((size_t)b * INC) * LL + i) * LL + j;
#pragma unroll 4
    for (int o = 0; o < INC; o++) {
        float s = s_b[o];
#pragma unroll
        for (int d = 0; d < DREL; d++) s = fmaf(T[d], s_Wr[o * DREL + d], s);
        float v = fmaf(m, pqp[(size_t)o * LL] + s_Q[o], s);
        outp[(size_t)o * (LL * LL)] = lrelu(v);
    }
}

// ============================================================================
// k_filt: g_filt2[b][d][f][kk] = leaky( fw1[row,:]·h[b] + fb1[row] )
// row = f*(256*9) + d*9 + kk ; 460800 rows total; warp does 4 rows x 8 batches
// ============================================================================
__global__ __launch_bounds__(256) void k_filt(const float* __restrict__ fw1,
                                              const float* __restrict__ fb1) {
    __shared__ float sh[BB * HIDN];
    int tid = threadIdx.x;
    for (int idx = tid; idx < BB * HIDN; idx += 256) sh[idx] = g_h[idx];
    __syncthreads();
    int wid = tid >> 5, lane = tid & 31;
    int rowbase = (blockIdx.x * 8 + wid) * 4;
    for (int q = 0; q < 4; q++) {
        int row = rowbase + q;
        const float* wr = fw1 + (size_t)row * HIDN;
        float acc[BB];
#pragma unroll
        for (int bb = 0; bb < BB; bb++) acc[bb] = 0.f;
        for (int k = lane; k < HIDN; k += 32) {
            float w = wr[k];
#pragma unroll
            for (int bb = 0; bb < BB; bb++) acc[bb] = fmaf(w, sh[bb * HIDN + k], acc[bb]);
        }
        float bias = fb1[row];
        int f = row / (INC * 9);
        int rem = row % (INC * 9);
        int dk = rem / 9, kk = rem % 9;
#pragma unroll
        for (int bb = 0; bb < BB; bb++) {
            float a = acc[bb];
            a += __shfl_down_sync(0xffffffffu, a, 16);
            a += __shfl_down_sync(0xffffffffu, a, 8);
            a += __shfl_down_sync(0xffffffffu, a, 4);
            a += __shfl_down_sync(0xffffffffu, a, 2);
            a += __shfl_down_sync(0xffffffffu, a, 1);
            if (lane == 0)
                g_filt2[(size_t)bb * (INC * FF * 9) + (size_t)dk * (FF * 9) + f * 9 + kk] =
                    lrelu(a + bias);
        }
    }
}

// ============================================================================
// k_conv: fused 3x3 VALID conv + spatial max (leaky applied after max).
// grid (y=126, ftile=5, b=8); 128 thr = 8 tf x 16 tx; thread: 5 filt x 8 x (f32x2)
// ============================================================================
__global__ __launch_bounds__(128) void k_conv() {
    int y = blockIdx.x;
    int fbase = blockIdx.y * 40;
    int b = blockIdx.z;
    __shared__ float s_in[3][132];
    __shared__ float s_filt[360];
    __shared__ float s_red[40 * 16];
    int tid = threadIdx.x;
    int tf = tid >> 4, tx = tid & 15;

    if (tid < 12) s_in[tid >> 2][128 + (tid & 3)] = 0.f;

    unsigned long long acc[5][4];
#pragma unroll
    for (int r = 0; r < 5; r++)
#pragma unroll
        for (int p = 0; p < 4; p++) acc[r][p] = 0ull;

    const float* gmb = g_mem + (((size_t)b * INC) * LL + y) * LL;
    const float* gfb = g_filt2 + (size_t)b * (INC * FF * 9) + fbase * 9;

    float p_in0 = gmb[tid], p_in1 = gmb[LL + tid], p_in2 = gmb[2 * LL + tid];
    float p_f0 = gfb[tid], p_f1 = gfb[128 + tid];
    float p_f2 = (tid < 104) ? gfb[256 + tid] : 0.f;

    for (int d = 0; d < INC; d++) {
        __syncthreads();
        s_in[0][tid] = p_in0;
        s_in[1][tid] = p_in1;
        s_in[2][tid] = p_in2;
        s_filt[tid] = p_f0;
        s_filt[128 + tid] = p_f1;
        if (tid < 104) s_filt[256 + tid] = p_f2;
        __syncthreads();
        if (d + 1 < INC) {
            const float* s = gmb + (size_t)(d + 1) * (LL * LL);
            p_in0 = s[tid];
            p_in1 = s[LL + tid];
            p_in2 = s[2 * LL + tid];
            const float* fs2 = gfb + (size_t)(d + 1) * (FF * 9);
            p_f0 = fs2[tid];
            p_f1 = fs2[128 + tid];
            if (tid < 104) p_f2 = fs2[256 + tid];
        }
#pragma unroll
        for (int ky = 0; ky < 3; ky++) {
            const float* rowp = &s_in[ky][tx * 8];
            float4 v0 = *(const float4*)(rowp);
            float4 v1 = *(const float4*)(rowp + 4);
            float2 v2 = *(const float2*)(rowp + 8);
            unsigned long long pr[9];
            PACKF2(pr[0], v0.x, v0.y);
            PACKF2(pr[1], v0.y, v0.z);
            PACKF2(pr[2], v0.z, v0.w);
            PACKF2(pr[3], v0.w, v1.x);
            PACKF2(pr[4], v1.x, v1.y);
            PACKF2(pr[5], v1.y, v1.z);
            PACKF2(pr[6], v1.z, v1.w);
            PACKF2(pr[7], v1.w, v2.x);
            PACKF2(pr[8], v2.x, v2.y);
#pragma unroll
            for (int rfi = 0; rfi < 5; rfi++) {
#pragma unroll
                for (int kx = 0; kx < 3; kx++) {
                    float fv = s_filt[(tf * 5 + rfi) * 9 + ky * 3 + kx];
                    unsigned long long fs;
                    PACKF2(fs, fv, fv);
                    FMA2(acc[rfi][0], pr[0 + kx], fs);
                    FMA2(acc[rfi][1], pr[2 + kx], fs);
                    FMA2(acc[rfi][2], pr[4 + kx], fs);
                    FMA2(acc[rfi][3], pr[6 + kx], fs);
                }
            }
        }
    }

#pragma unroll
    for (int rfi = 0; rfi < 5; rfi++) {
        float mx = -3.4e38f;
#pragma unroll
        for (int px = 0; px < 4; px++) {
            float v0, v1;
            UNPACKF2(v0, v1, acc[rfi][px]);
            int x0 = tx * 8 + 2 * px;
            if (x0 < OSP) mx = fmaxf(mx, v0);
            if (x0 + 1 < OSP) mx = fmaxf(mx, v1);
        }
        s_red[(tf * 5 + rfi) * 16 + tx] = mx;
    }
    __syncthreads();
    if (tid < 40) {
        float m = -3.4e38f;
#pragma unroll
        for (int t = 0; t < 16; t++) m = fmaxf(m, s_red[tid * 16 + t]);
        atomicMaxF(&g_maxv[b * FF + fbase + tid], m);
    }
}

// ============================================================================
__global__ void k_final(float* __restrict__ out) {
    int t = blockIdx.x * blockDim.x + threadIdx.x;
    if (t < BB * FF) out[t] = g_trans[t] + lrelu(g_maxv[t]);
}

extern "C" void kernel_launch(void* const* d_in, const int* in_sizes, int n_in,
                              void* d_out, int out_size) {
    (void)in_sizes; (void)n_in; (void)out_size;
    const float* energy = (const float*)d_in[0];
    const float* word_h = (const float*)d_in[1];
    const float* e1     = (const float*)d_in[2];
    const float* e2     = (const float*)d_in[3];
    // d_in[4] = sent_len (unused)
    const float* rel_embs = (const float*)d_in[5];
    const float* arc_W    = (const float*)d_in[6];
    const float* arc_b    = (const float*)d_in[7];
    const float* ff_W     = (const float*)d_in[8];
    const float* ff_b     = (const float*)d_in[9];
    const float* fw1      = (const float*)d_in[10];
    const float* fb1      = (const float*)d_in[11];
    const float* it_W     = (const float*)d_in[12];
    const float* it_b     = (const float*)d_in[13];
    float* out = (float*)d_out;

    k_small<<<500, 256>>>(e1, e2, ff_W, ff_b, it_W, it_b);
    k_pq<<<dim3(2, 8, BB), 256>>>(word_h, arc_W);
    k_arc<<<dim3(LL, BB), 128>>>(energy, rel_embs, arc_W, arc_b);
    k_filt<<<14400, 256>>>(fw1, fb1);
    k_conv<<<dim3(OSP, 5, BB), 128>>>();
    k_final<<<(BB * FF + 255) / 256, 256>>>(out);
}